// round 15
// baseline (speedup 1.0000x reference)
#include <cuda_runtime.h>
#include <cuda_fp16.h>
#include <cstdint>
#include <math.h>

// Problem constants
#define BATCH 8
#define SEQ   4096
#define DMODEL 512
#define NSTATE 64
#define TOKENS (BATCH*SEQ)          // 32768
#define NCHUNKS 128
#define CHUNK  (SEQ/NCHUNKS)        // 32
#define LN_EPS 1e-3f
#define KCAT   (NSTATE + DMODEL)    // 576

// ---------------- device scratch ----------------
__device__ __half g_xn [ (size_t)TOKENS * DMODEL ];   // LN out (fp16)
__device__ __half g_cat[ (size_t)TOKENS * KCAT ];     // [ch | xp] fp16, K=576
__device__ __half g_bcx[ (size_t)TOKENS * 192 ];      // [B|C|xs] fp16 (scan input)
__device__ __half g_WTin   [ DMODEL * DMODEL ];       // [N,K]
__device__ __half g_WTcat  [ 192 * DMODEL ];
__device__ __half g_WTfused[ DMODEL * KCAT ];         // [N=512, K=576]: [Wso@Wout | D*Wout]
__device__ float  g_bcat [ 192 ];
__device__ float  g_chunkend[ BATCH * NCHUNKS * NSTATE ];
__device__ float  g_hinit   [ BATCH * NCHUNKS * NSTATE ];

// ---------------- PTX helpers ----------------
__device__ __forceinline__ uint32_t smem_u32(const void* p) {
    uint32_t a;
    asm("{ .reg .u64 t; cvta.to.shared.u64 t, %1; cvt.u32.u64 %0, t; }" : "=r"(a) : "l"(p));
    return a;
}
__device__ __forceinline__ void cp16(uint32_t dst, const void* src) {
    asm volatile("cp.async.cg.shared.global [%0], [%1], 16;" :: "r"(dst), "l"(src));
}
#define CP_COMMIT()  asm volatile("cp.async.commit_group;" ::: "memory")
#define CP_WAIT1()   asm volatile("cp.async.wait_group 1;" ::: "memory")

__device__ __forceinline__ void ldsm4(uint32_t* r, uint32_t addr) {
    asm volatile("ldmatrix.sync.aligned.m8n8.x4.shared.b16 {%0,%1,%2,%3}, [%4];"
        : "=r"(r[0]), "=r"(r[1]), "=r"(r[2]), "=r"(r[3]) : "r"(addr));
}
__device__ __forceinline__ void mma16(float* d, uint32_t a0, uint32_t a1, uint32_t a2,
                                      uint32_t a3, uint32_t b0, uint32_t b1) {
    asm volatile(
        "mma.sync.aligned.m16n8k16.row.col.f32.f16.f16.f32 "
        "{%0,%1,%2,%3}, {%4,%5,%6,%7}, {%8,%9}, {%0,%1,%2,%3};"
        : "+f"(d[0]), "+f"(d[1]), "+f"(d[2]), "+f"(d[3])
        : "r"(a0), "r"(a1), "r"(a2), "r"(a3), "r"(b0), "r"(b1));
}

// ---------------- fp16 mma.sync GEMM: BM=128 x BN, BK=64, 3-stage ----------------
// WM = warp-tile M (64 -> 2x4 warp grid, 32 -> 4x2). WN = 32.
// 128B smem rows, XOR-16B-chunk swizzle. fp32 accum. A stride lda, C stride ldc.
// EPI 0: + bias[col];  EPI 2: + bias[col] + aux[row*ldc+col]
// HOUT: store C as fp16
template<int BN, int WM, int EPI, int HOUT>
__global__ void __launch_bounds__(256, (BN == 64) ? 3 : 2)
mma_gemm(const __half* __restrict__ A, int lda,
         const __half* __restrict__ BT,
         void* __restrict__ Cv_, int ldc,
         const float* __restrict__ bias, const float* __restrict__ aux,
         int K, int N) {
    constexpr int BM = 128, BK = 64, ST = 3;
    constexpr int ROWB = 128;               // 64 halves per row
    constexpr int R  = BM / WM;             // warp rows
    constexpr int C  = 8 / R;               // warp cols
    constexpr int WN = BN / C;              // warp tile N (=32)
    constexpr int MT = WM / 16;
    constexpr int NT = WN / 8;
    constexpr int NP = NT / 2;
    constexpr int ABUF = BM * ROWB, BBUF = BN * ROWB;
    extern __shared__ __half smh[];
    const uint32_t sA0 = smem_u32(smh);
    const uint32_t sB0 = sA0 + ST * ABUF;

    const int tid  = threadIdx.x;
    const int lane = tid & 31;
    const int wid  = tid >> 5;
    const int wm   = wid % R;
    const int wn   = wid / R;
    const int g    = lane >> 2;
    const int t    = lane & 3;
    const int m0   = blockIdx.y * BM;
    const int n0   = blockIdx.x * BN;
    const int S    = K / BK;

    const int crow = tid >> 3, cch = tid & 7;
    const int csw  = (cch ^ (crow & 7)) << 4;
    const __half* Asrc = A  + (size_t)(m0 + crow) * lda + cch * 8;
    const __half* Bsrc = BT + (size_t)(n0 + crow) * K + cch * 8;
    const uint32_t adst = sA0 + crow * ROWB + csw;
    const uint32_t bdst = sB0 + crow * ROWB + csw;

    auto load_stage = [&](int s) {
        int buf = s % ST;
        const __half* pa = Asrc + s * BK;
        const __half* pb = Bsrc + s * BK;
        uint32_t da = adst + buf * ABUF;
        uint32_t db = bdst + buf * BBUF;
        #pragma unroll
        for (int it = 0; it < 4; it++)
            cp16(da + it * 32 * ROWB, pa + (size_t)it * 32 * lda);
        #pragma unroll
        for (int it = 0; it < BN / 32; it++)
            cp16(db + it * 32 * ROWB, pb + (size_t)it * 32 * K);
        CP_COMMIT();
    };

    float d[MT][NT][4];
    #pragma unroll
    for (int mt = 0; mt < MT; mt++)
        #pragma unroll
        for (int nt = 0; nt < NT; nt++)
            #pragma unroll
            for (int j = 0; j < 4; j++) d[mt][nt][j] = 0.0f;

    const int lx7 = lane & 7;
    const uint32_t a_rowb = sA0 + (wm * WM + (lane & 15)) * ROWB;
    const int a_ch0 = lane >> 4;
    const uint32_t b_rowb0 = sB0 + (wn * WN + (lane & 7) + ((lane >> 4) & 1) * 8) * ROWB;
    const int b_ch0 = (lane >> 3) & 1;

    load_stage(0);
    if (S > 1) load_stage(1); else CP_COMMIT();

    for (int s = 0; s < S; s++) {
        CP_WAIT1();
        __syncthreads();
        int buf = s % ST;
        const uint32_t aoff = buf * ABUF;
        const uint32_t boff = buf * BBUF;

        if (s + 2 < S) load_stage(s + 2); else CP_COMMIT();

        #pragma unroll
        for (int kc = 0; kc < 4; kc++) {
            uint32_t af[MT][4], bf[NP][4];
            const int asw = ((a_ch0 + kc * 2) ^ lx7) << 4;
            const int bsw = ((b_ch0 + kc * 2) ^ lx7) << 4;
            #pragma unroll
            for (int mt = 0; mt < MT; mt++)
                ldsm4(af[mt], a_rowb + aoff + mt * 16 * ROWB + asw);
            #pragma unroll
            for (int np = 0; np < NP; np++)
                ldsm4(bf[np], b_rowb0 + boff + np * 16 * ROWB + bsw);
            #pragma unroll
            for (int mt = 0; mt < MT; mt++)
                #pragma unroll
                for (int np = 0; np < NP; np++) {
                    mma16(d[mt][2 * np], af[mt][0], af[mt][1], af[mt][2], af[mt][3],
                          bf[np][0], bf[np][1]);
                    mma16(d[mt][2 * np + 1], af[mt][0], af[mt][1], af[mt][2], af[mt][3],
                          bf[np][2], bf[np][3]);
                }
        }
    }

    // ---- epilogue ----
    #pragma unroll
    for (int mt = 0; mt < MT; mt++) {
        int row = m0 + wm * WM + mt * 16 + g;
        #pragma unroll
        for (int nt = 0; nt < NT; nt++) {
            int col = n0 + wn * WN + nt * 8 + 2 * t;
            float2 b2 = *reinterpret_cast<const float2*>(bias + col);
            size_t off0 = (size_t)row * ldc + col;
            size_t off1 = (size_t)(row + 8) * ldc + col;
            float2 v0 = make_float2(d[mt][nt][0], d[mt][nt][1]);
            float2 v1 = make_float2(d[mt][nt][2], d[mt][nt][3]);
            if (EPI == 0) {
                v0.x += b2.x; v0.y += b2.y;
                v1.x += b2.x; v1.y += b2.y;
            } else {
                float2 a0 = *reinterpret_cast<const float2*>(aux + off0);
                float2 a1 = *reinterpret_cast<const float2*>(aux + off1);
                v0.x += b2.x + a0.x; v0.y += b2.y + a0.y;
                v1.x += b2.x + a1.x; v1.y += b2.y + a1.y;
            }
            if (HOUT) {
                __half* Ch = (__half*)Cv_;
                *reinterpret_cast<__half2*>(Ch + off0) = __floats2half2_rn(v0.x, v0.y);
                *reinterpret_cast<__half2*>(Ch + off1) = __floats2half2_rn(v1.x, v1.y);
            } else {
                float* Cf = (float*)Cv_;
                *reinterpret_cast<float2*>(Cf + off0) = v0;
                *reinterpret_cast<float2*>(Cf + off1) = v1;
            }
        }
    }
}

// ---------------- coalesced transpose: W_in -> WTin, D*W_out -> WTfused tail ----------------
__global__ void prep_transpose(const float* __restrict__ W_in, const float* __restrict__ W_out,
                               const float* __restrict__ D_skip) {
    __shared__ float t1[32][33], t2[32][33];
    int tx = threadIdx.x, ty = threadIdx.y;          // 32 x 8
    int x = blockIdx.x * 32 + tx;                    // col (n) in source
    int y0 = blockIdx.y * 32;                        // row (k) base
    #pragma unroll
    for (int j = 0; j < 32; j += 8) {
        int k = y0 + ty + j;
        t1[ty + j][tx] = W_in[(size_t)k * DMODEL + x];
        t2[ty + j][tx] = D_skip[k] * W_out[(size_t)k * DMODEL + x];
    }
    __syncthreads();
    int n = blockIdx.x * 32;                         // output row base (n)
    int k2 = blockIdx.y * 32 + tx;                   // output col (k)
    #pragma unroll
    for (int j = 0; j < 32; j += 8) {
        g_WTin  [(size_t)(n + ty + j) * DMODEL + k2]        = __float2half(t1[tx][ty + j]);
        g_WTfused[(size_t)(n + ty + j) * KCAT + NSTATE + k2] = __float2half(t2[tx][ty + j]);
    }
}

// ---------------- small weight prep: concat proj weights + biases ----------------
__global__ void prep_weights(const float* __restrict__ W_B, const float* __restrict__ W_C,
                             const float* __restrict__ W_xs,
                             const float* __restrict__ b_B, const float* __restrict__ b_C) {
    int idx = blockIdx.x * 256 + threadIdx.x;
    if (idx < 192 * DMODEL) {
        int n = idx >> 9, k = idx & 511;
        float v;
        if (n < 64)       v = W_B [k * 64 + n];
        else if (n < 128) v = W_C [k * 64 + (n - 64)];
        else              v = W_xs[k * 64 + (n - 128)];
        g_WTcat[n * DMODEL + k] = __float2half(v);
    }
    if (idx < 192) g_bcat[idx] = (idx < 64) ? b_B[idx] : (idx < 128 ? b_C[idx - 64] : 0.0f);
}

// fused head: (W_so @ W_out)[k, n], k in 0..63 — block = k, threads = n
__global__ void prep_fused(const float* __restrict__ W_so, const float* __restrict__ W_out) {
    __shared__ float srow[DMODEL];
    int k = blockIdx.x;
    int n = threadIdx.x;
    for (int j = n; j < DMODEL; j += 512) srow[j] = W_so[k * DMODEL + j];
    __syncthreads();
    float acc = 0.0f;
    #pragma unroll 8
    for (int j = 0; j < DMODEL; j++)
        acc = fmaf(srow[j], W_out[j * DMODEL + n], acc);
    g_WTfused[n * KCAT + k] = __float2half(acc);
}

// ---------------- LayerNorm: warp-per-token, shuffle-only -> fp16 ----------------
__global__ void __launch_bounds__(128)
ln_kernel(const float* __restrict__ x,
          const float* __restrict__ gamma,
          const float* __restrict__ beta) {
    const int token = (blockIdx.x * 128 + threadIdx.x) >> 5;
    const int lane  = threadIdx.x & 31;

    const float4* xr = reinterpret_cast<const float4*>(x) + (size_t)token * 128 + lane * 4;
    float4 v[4];
    #pragma unroll
    for (int i = 0; i < 4; i++) v[i] = xr[i];

    float s = 0.0f, q = 0.0f;
    #pragma unroll
    for (int i = 0; i < 4; i++) {
        s += v[i].x + v[i].y + v[i].z + v[i].w;
        q += v[i].x*v[i].x + v[i].y*v[i].y + v[i].z*v[i].z + v[i].w*v[i].w;
    }
    #pragma unroll
    for (int o = 16; o; o >>= 1) {
        s += __shfl_xor_sync(0xffffffffu, s, o);
        q += __shfl_xor_sync(0xffffffffu, q, o);
    }
    float mu  = s * (1.0f / DMODEL);
    float var = q * (1.0f / DMODEL) - mu * mu;
    float inv = rsqrtf(var + LN_EPS);

    const float4* gv4 = reinterpret_cast<const float4*>(gamma) + lane * 4;
    const float4* bv4 = reinterpret_cast<const float4*>(beta)  + lane * 4;
    __half2 h[8];
    #pragma unroll
    for (int i = 0; i < 4; i++) {
        float4 gv = gv4[i], bv = bv4[i];
        h[2*i]   = __floats2half2_rn((v[i].x - mu) * inv * gv.x + bv.x,
                                     (v[i].y - mu) * inv * gv.y + bv.y);
        h[2*i+1] = __floats2half2_rn((v[i].z - mu) * inv * gv.z + bv.z,
                                     (v[i].w - mu) * inv * gv.w + bv.w);
    }
    uint4* outp = reinterpret_cast<uint4*>(g_xn + (size_t)token * DMODEL + lane * 16);
    outp[0] = *reinterpret_cast<uint4*>(&h[0]);
    outp[1] = *reinterpret_cast<uint4*>(&h[4]);
}

// ---------------- chunked SSM scan (fp32 math, fp16 inputs) ----------------
__global__ void scan_passA(const float* __restrict__ A_log) {
    int b = blockIdx.x / NCHUNKS;
    int c = blockIdx.x % NCHUNKS;
    int n = threadIdx.x;
    float Ab = expf(-expf(A_log[n]));
    const __half* base = g_bcx + (size_t)(b * SEQ + c * CHUNK) * 192;
    float h = 0.0f;
    #pragma unroll 8
    for (int t = 0; t < CHUNK; t++) {
        float Bv = __half2float(base[(size_t)t * 192 + n]);
        float xv = __half2float(base[(size_t)t * 192 + 128 + n]);
        h = fmaf(Ab, h, Bv * xv);
    }
    g_chunkend[(b * NCHUNKS + c) * NSTATE + n] = h;
}

__global__ void scan_passB(const float* __restrict__ A_log) {
    int idx = threadIdx.x;
    int b = idx / NSTATE;
    int n = idx % NSTATE;
    float AL = expf(-(float)CHUNK * expf(A_log[n]));
    float h = 0.0f;
    for (int c = 0; c < NCHUNKS; c++) {
        g_hinit[(b * NCHUNKS + c) * NSTATE + n] = h;
        h = fmaf(AL, h, g_chunkend[(b * NCHUNKS + c) * NSTATE + n]);
    }
}

// out: fp16 ch into g_cat cols 0..63
__global__ void scan_passC(const float* __restrict__ A_log) {
    int b = blockIdx.x / NCHUNKS;
    int c = blockIdx.x % NCHUNKS;
    int n = threadIdx.x;
    float Ab = expf(-expf(A_log[n]));
    const __half* base = g_bcx + (size_t)(b * SEQ + c * CHUNK) * 192;
    __half* out = g_cat + (size_t)(b * SEQ + c * CHUNK) * KCAT;
    float h = g_hinit[(b * NCHUNKS + c) * NSTATE + n];
    #pragma unroll 8
    for (int t = 0; t < CHUNK; t++) {
        float Bv = __half2float(base[(size_t)t * 192 + n]);
        float Cv = __half2float(base[(size_t)t * 192 + 64 + n]);
        float xv = __half2float(base[(size_t)t * 192 + 128 + n]);
        h = fmaf(Ab, h, Bv * xv);
        out[(size_t)t * KCAT + n] = __float2half(Cv * h);
    }
}

// ---------------- launch ----------------
extern "C" void kernel_launch(void* const* d_in, const int* in_sizes, int n_in,
                              void* d_out, int out_size) {
    const float* x        = (const float*)d_in[0];
    const float* ln_gamma = (const float*)d_in[1];
    const float* ln_beta  = (const float*)d_in[2];
    const float* W_in     = (const float*)d_in[3];
    const float* b_in     = (const float*)d_in[4];
    const float* W_xs     = (const float*)d_in[5];
    const float* W_B      = (const float*)d_in[6];
    const float* b_B      = (const float*)d_in[7];
    const float* W_C      = (const float*)d_in[8];
    const float* b_C      = (const float*)d_in[9];
    const float* A_log    = (const float*)d_in[10];
    const float* D_skip   = (const float*)d_in[11];
    const float* W_so     = (const float*)d_in[12];
    const float* W_out    = (const float*)d_in[13];
    const float* b_out    = (const float*)d_in[14];
    float* out = (float*)d_out;

    __half* xn;     cudaGetSymbolAddress((void**)&xn,     g_xn);
    __half* cat;    cudaGetSymbolAddress((void**)&cat,    g_cat);
    __half* bcx;    cudaGetSymbolAddress((void**)&bcx,    g_bcx);
    __half* WTin;   cudaGetSymbolAddress((void**)&WTin,   g_WTin);
    __half* WTcat;  cudaGetSymbolAddress((void**)&WTcat,  g_WTcat);
    __half* WTfused;cudaGetSymbolAddress((void**)&WTfused,g_WTfused);
    float* bcat;    cudaGetSymbolAddress((void**)&bcat,   g_bcat);

    const int SMEM64  = 3 * (128 + 64) * 128;    // 73728
    const int SMEM128 = 3 * (128 + 128) * 128;   // 98304
    cudaFuncSetAttribute(mma_gemm<128, 64, 0, 1>, cudaFuncAttributeMaxDynamicSharedMemorySize, SMEM128);
    cudaFuncSetAttribute(mma_gemm<64, 32, 0, 1>,  cudaFuncAttributeMaxDynamicSharedMemorySize, SMEM64);
    cudaFuncSetAttribute(mma_gemm<128, 64, 2, 0>, cudaFuncAttributeMaxDynamicSharedMemorySize, SMEM128);

    // 1) weight prep
    prep_transpose<<<dim3(16, 16), dim3(32, 8)>>>(W_in, W_out, D_skip);
    prep_weights<<<(192 * DMODEL + 255) / 256, 256>>>(W_B, W_C, W_xs, b_B, b_C);
    prep_fused<<<NSTATE, 512>>>(W_so, W_out);

    // 2) LayerNorm -> fp16 (warp per token)
    ln_kernel<<<TOKENS / 4, 128>>>(x, ln_gamma, ln_beta);

    // 3) xp = xn @ W_in + b_in -> g_cat cols 64..575 (fp16)
    mma_gemm<128, 64, 0, 1><<<dim3(4, 256), 256, SMEM128>>>(
        xn, DMODEL, WTin, cat + NSTATE, KCAT, b_in, nullptr, DMODEL, DMODEL);

    // 4) [B|C|xs] = xp @ Wcat + bcat (fp16 -> scan), warp tile 32x32
    mma_gemm<64, 32, 0, 1><<<dim3(3, 256), 256, SMEM64>>>(
        cat + NSTATE, KCAT, WTcat, bcx, 192, bcat, nullptr, DMODEL, 192);

    // 5) chunked scan -> ch = fp16(C*h) into g_cat cols 0..63
    scan_passA<<<BATCH * NCHUNKS, NSTATE>>>(A_log);
    scan_passB<<<1, BATCH * NSTATE>>>(A_log);
    scan_passC<<<BATCH * NCHUNKS, NSTATE>>>(A_log);

    // 6) out = [ch | xp] @ WTfused + b_out + x   (K=576, fp32 out)
    mma_gemm<128, 64, 2, 0><<<dim3(4, 256), 256, SMEM128>>>(
        cat, KCAT, WTfused, out, DMODEL, b_out, x, KCAT, DMODEL);
}

// round 16
// speedup vs baseline: 1.0388x; 1.0388x over previous
#include <cuda_runtime.h>
#include <cuda_fp16.h>
#include <cstdint>
#include <math.h>

// Problem constants
#define BATCH 8
#define SEQ   4096
#define DMODEL 512
#define NSTATE 64
#define TOKENS (BATCH*SEQ)          // 32768
#define NCHUNKS 128
#define CHUNK  (SEQ/NCHUNKS)        // 32
#define LN_EPS 1e-3f
#define KCAT   (NSTATE + DMODEL)    // 576

// ---------------- device scratch ----------------
__device__ __half g_xn [ (size_t)TOKENS * DMODEL ];   // LN out (fp16)
__device__ __half g_cat[ (size_t)TOKENS * KCAT ];     // [ch | xp] fp16, K=576
__device__ __half g_bcx[ (size_t)TOKENS * 192 ];      // [B|C|xs] fp16 (scan input)
__device__ __half g_WTin   [ DMODEL * DMODEL ];       // [N,K]
__device__ __half g_WTcat  [ 192 * DMODEL ];
__device__ __half g_WTfused[ DMODEL * KCAT ];         // [N=512, K=576]: [Wso@Wout | D*Wout]
__device__ float  g_bcat [ 192 ];
__device__ float  g_chunkend[ BATCH * NCHUNKS * NSTATE ];
__device__ float  g_hinit   [ BATCH * NCHUNKS * NSTATE ];

// ---------------- PTX helpers ----------------
__device__ __forceinline__ uint32_t smem_u32(const void* p) {
    uint32_t a;
    asm("{ .reg .u64 t; cvta.to.shared.u64 t, %1; cvt.u32.u64 %0, t; }" : "=r"(a) : "l"(p));
    return a;
}
__device__ __forceinline__ void cp16(uint32_t dst, const void* src) {
    asm volatile("cp.async.cg.shared.global [%0], [%1], 16;" :: "r"(dst), "l"(src));
}
#define CP_COMMIT()  asm volatile("cp.async.commit_group;" ::: "memory")
#define CP_WAIT1()   asm volatile("cp.async.wait_group 1;" ::: "memory")

__device__ __forceinline__ void ldsm4(uint32_t* r, uint32_t addr) {
    asm volatile("ldmatrix.sync.aligned.m8n8.x4.shared.b16 {%0,%1,%2,%3}, [%4];"
        : "=r"(r[0]), "=r"(r[1]), "=r"(r[2]), "=r"(r[3]) : "r"(addr));
}
__device__ __forceinline__ void mma16(float* d, uint32_t a0, uint32_t a1, uint32_t a2,
                                      uint32_t a3, uint32_t b0, uint32_t b1) {
    asm volatile(
        "mma.sync.aligned.m16n8k16.row.col.f32.f16.f16.f32 "
        "{%0,%1,%2,%3}, {%4,%5,%6,%7}, {%8,%9}, {%0,%1,%2,%3};"
        : "+f"(d[0]), "+f"(d[1]), "+f"(d[2]), "+f"(d[3])
        : "r"(a0), "r"(a1), "r"(a2), "r"(a3), "r"(b0), "r"(b1));
}

// ---------------- fp16 mma.sync GEMM: BM=128 x BN, BK=64, 3-stage ----------------
// WM = warp-tile M (64 -> 2x4 warp grid, 32 -> 4x2). WN = 32.
// 128B smem rows, XOR-16B-chunk swizzle. fp32 accum. A stride lda, C stride ldc.
// EPI 0: + bias[col];  EPI 2: + bias[col] + aux[row*ldc+col]
// HOUT: store C as fp16
template<int BN, int WM, int EPI, int HOUT>
__global__ void __launch_bounds__(256, (BN == 64) ? 3 : 2)
mma_gemm(const __half* __restrict__ A, int lda,
         const __half* __restrict__ BT,
         void* __restrict__ Cv_, int ldc,
         const float* __restrict__ bias, const float* __restrict__ aux,
         int K, int N) {
    constexpr int BM = 128, BK = 64, ST = 3;
    constexpr int ROWB = 128;               // 64 halves per row
    constexpr int R  = BM / WM;             // warp rows
    constexpr int C  = 8 / R;               // warp cols
    constexpr int WN = BN / C;              // warp tile N (=32)
    constexpr int MT = WM / 16;
    constexpr int NT = WN / 8;
    constexpr int NP = NT / 2;
    constexpr int ABUF = BM * ROWB, BBUF = BN * ROWB;
    extern __shared__ __half smh[];
    const uint32_t sA0 = smem_u32(smh);
    const uint32_t sB0 = sA0 + ST * ABUF;

    const int tid  = threadIdx.x;
    const int lane = tid & 31;
    const int wid  = tid >> 5;
    const int wm   = wid % R;
    const int wn   = wid / R;
    const int g    = lane >> 2;
    const int t    = lane & 3;
    const int m0   = blockIdx.y * BM;
    const int n0   = blockIdx.x * BN;
    const int S    = K / BK;

    const int crow = tid >> 3, cch = tid & 7;
    const int csw  = (cch ^ (crow & 7)) << 4;
    const __half* Asrc = A  + (size_t)(m0 + crow) * lda + cch * 8;
    const __half* Bsrc = BT + (size_t)(n0 + crow) * K + cch * 8;
    const uint32_t adst = sA0 + crow * ROWB + csw;
    const uint32_t bdst = sB0 + crow * ROWB + csw;

    auto load_stage = [&](int s) {
        int buf = s % ST;
        const __half* pa = Asrc + s * BK;
        const __half* pb = Bsrc + s * BK;
        uint32_t da = adst + buf * ABUF;
        uint32_t db = bdst + buf * BBUF;
        #pragma unroll
        for (int it = 0; it < 4; it++)
            cp16(da + it * 32 * ROWB, pa + (size_t)it * 32 * lda);
        #pragma unroll
        for (int it = 0; it < BN / 32; it++)
            cp16(db + it * 32 * ROWB, pb + (size_t)it * 32 * K);
        CP_COMMIT();
    };

    float d[MT][NT][4];
    #pragma unroll
    for (int mt = 0; mt < MT; mt++)
        #pragma unroll
        for (int nt = 0; nt < NT; nt++)
            #pragma unroll
            for (int j = 0; j < 4; j++) d[mt][nt][j] = 0.0f;

    const int lx7 = lane & 7;
    const uint32_t a_rowb = sA0 + (wm * WM + (lane & 15)) * ROWB;
    const int a_ch0 = lane >> 4;
    const uint32_t b_rowb0 = sB0 + (wn * WN + (lane & 7) + ((lane >> 4) & 1) * 8) * ROWB;
    const int b_ch0 = (lane >> 3) & 1;

    load_stage(0);
    if (S > 1) load_stage(1); else CP_COMMIT();

    for (int s = 0; s < S; s++) {
        CP_WAIT1();
        __syncthreads();
        int buf = s % ST;
        const uint32_t aoff = buf * ABUF;
        const uint32_t boff = buf * BBUF;

        if (s + 2 < S) load_stage(s + 2); else CP_COMMIT();

        #pragma unroll
        for (int kc = 0; kc < 4; kc++) {
            uint32_t af[MT][4], bf[NP][4];
            const int asw = ((a_ch0 + kc * 2) ^ lx7) << 4;
            const int bsw = ((b_ch0 + kc * 2) ^ lx7) << 4;
            #pragma unroll
            for (int mt = 0; mt < MT; mt++)
                ldsm4(af[mt], a_rowb + aoff + mt * 16 * ROWB + asw);
            #pragma unroll
            for (int np = 0; np < NP; np++)
                ldsm4(bf[np], b_rowb0 + boff + np * 16 * ROWB + bsw);
            #pragma unroll
            for (int mt = 0; mt < MT; mt++)
                #pragma unroll
                for (int np = 0; np < NP; np++) {
                    mma16(d[mt][2 * np], af[mt][0], af[mt][1], af[mt][2], af[mt][3],
                          bf[np][0], bf[np][1]);
                    mma16(d[mt][2 * np + 1], af[mt][0], af[mt][1], af[mt][2], af[mt][3],
                          bf[np][2], bf[np][3]);
                }
        }
    }

    // ---- epilogue ----
    #pragma unroll
    for (int mt = 0; mt < MT; mt++) {
        int row = m0 + wm * WM + mt * 16 + g;
        #pragma unroll
        for (int nt = 0; nt < NT; nt++) {
            int col = n0 + wn * WN + nt * 8 + 2 * t;
            float2 b2 = *reinterpret_cast<const float2*>(bias + col);
            size_t off0 = (size_t)row * ldc + col;
            size_t off1 = (size_t)(row + 8) * ldc + col;
            float2 v0 = make_float2(d[mt][nt][0], d[mt][nt][1]);
            float2 v1 = make_float2(d[mt][nt][2], d[mt][nt][3]);
            if (EPI == 0) {
                v0.x += b2.x; v0.y += b2.y;
                v1.x += b2.x; v1.y += b2.y;
            } else {
                float2 a0 = *reinterpret_cast<const float2*>(aux + off0);
                float2 a1 = *reinterpret_cast<const float2*>(aux + off1);
                v0.x += b2.x + a0.x; v0.y += b2.y + a0.y;
                v1.x += b2.x + a1.x; v1.y += b2.y + a1.y;
            }
            if (HOUT) {
                __half* Ch = (__half*)Cv_;
                *reinterpret_cast<__half2*>(Ch + off0) = __floats2half2_rn(v0.x, v0.y);
                *reinterpret_cast<__half2*>(Ch + off1) = __floats2half2_rn(v1.x, v1.y);
            } else {
                float* Cf = (float*)Cv_;
                *reinterpret_cast<float2*>(Cf + off0) = v0;
                *reinterpret_cast<float2*>(Cf + off1) = v1;
            }
        }
    }
}

// ---------------- coalesced transpose: W_in -> WTin, D*W_out -> WTfused tail ----------------
__global__ void prep_transpose(const float* __restrict__ W_in, const float* __restrict__ W_out,
                               const float* __restrict__ D_skip) {
    __shared__ float t1[32][33], t2[32][33];
    int tx = threadIdx.x, ty = threadIdx.y;          // 32 x 8
    int x = blockIdx.x * 32 + tx;                    // col (n) in source
    int y0 = blockIdx.y * 32;                        // row (k) base
    #pragma unroll
    for (int j = 0; j < 32; j += 8) {
        int k = y0 + ty + j;
        t1[ty + j][tx] = W_in[(size_t)k * DMODEL + x];
        t2[ty + j][tx] = D_skip[k] * W_out[(size_t)k * DMODEL + x];
    }
    __syncthreads();
    int n = blockIdx.x * 32;                         // output row base (n)
    int k2 = blockIdx.y * 32 + tx;                   // output col (k)
    #pragma unroll
    for (int j = 0; j < 32; j += 8) {
        g_WTin  [(size_t)(n + ty + j) * DMODEL + k2]        = __float2half(t1[tx][ty + j]);
        g_WTfused[(size_t)(n + ty + j) * KCAT + NSTATE + k2] = __float2half(t2[tx][ty + j]);
    }
}

// ---------------- small weight prep: concat proj weights + biases ----------------
__global__ void prep_weights(const float* __restrict__ W_B, const float* __restrict__ W_C,
                             const float* __restrict__ W_xs,
                             const float* __restrict__ b_B, const float* __restrict__ b_C) {
    int idx = blockIdx.x * 256 + threadIdx.x;
    if (idx < 192 * DMODEL) {
        int n = idx >> 9, k = idx & 511;
        float v;
        if (n < 64)       v = W_B [k * 64 + n];
        else if (n < 128) v = W_C [k * 64 + (n - 64)];
        else              v = W_xs[k * 64 + (n - 128)];
        g_WTcat[n * DMODEL + k] = __float2half(v);
    }
    if (idx < 192) g_bcat[idx] = (idx < 64) ? b_B[idx] : (idx < 128 ? b_C[idx - 64] : 0.0f);
}

// fused head: (W_so @ W_out)[k, n], k in 0..63 — block = k, threads = n
__global__ void prep_fused(const float* __restrict__ W_so, const float* __restrict__ W_out) {
    __shared__ float srow[DMODEL];
    int k = blockIdx.x;
    int n = threadIdx.x;
    for (int j = n; j < DMODEL; j += 512) srow[j] = W_so[k * DMODEL + j];
    __syncthreads();
    float acc = 0.0f;
    #pragma unroll 8
    for (int j = 0; j < DMODEL; j++)
        acc = fmaf(srow[j], W_out[j * DMODEL + n], acc);
    g_WTfused[n * KCAT + k] = __float2half(acc);
}

// ---------------- LayerNorm: warp-per-token, COALESCED interleaved access ----------------
// lane reads float4 #(lane + 32*k): unit inter-lane stride -> one wavefront per LDG.128.
__global__ void __launch_bounds__(256)
ln_kernel(const float* __restrict__ x,
          const float* __restrict__ gamma,
          const float* __restrict__ beta) {
    const int token = (blockIdx.x * 256 + threadIdx.x) >> 5;
    const int lane  = threadIdx.x & 31;

    const float4* xr = reinterpret_cast<const float4*>(x) + (size_t)token * 128 + lane;
    float4 v[4];
    #pragma unroll
    for (int i = 0; i < 4; i++) v[i] = xr[i * 32];

    float s = 0.0f, q = 0.0f;
    #pragma unroll
    for (int i = 0; i < 4; i++) {
        s += v[i].x + v[i].y + v[i].z + v[i].w;
        q += v[i].x*v[i].x + v[i].y*v[i].y + v[i].z*v[i].z + v[i].w*v[i].w;
    }
    #pragma unroll
    for (int o = 16; o; o >>= 1) {
        s += __shfl_xor_sync(0xffffffffu, s, o);
        q += __shfl_xor_sync(0xffffffffu, q, o);
    }
    float mu  = s * (1.0f / DMODEL);
    float var = q * (1.0f / DMODEL) - mu * mu;
    float inv = rsqrtf(var + LN_EPS);

    const float4* gv4 = reinterpret_cast<const float4*>(gamma) + lane;
    const float4* bv4 = reinterpret_cast<const float4*>(beta)  + lane;
    uint2* outp = reinterpret_cast<uint2*>(g_xn + (size_t)token * DMODEL) + lane;
    #pragma unroll
    for (int i = 0; i < 4; i++) {
        float4 gv = gv4[i * 32], bv = bv4[i * 32];
        __half2 h0 = __floats2half2_rn((v[i].x - mu) * inv * gv.x + bv.x,
                                       (v[i].y - mu) * inv * gv.y + bv.y);
        __half2 h1 = __floats2half2_rn((v[i].z - mu) * inv * gv.z + bv.z,
                                       (v[i].w - mu) * inv * gv.w + bv.w);
        uint2 u;
        u.x = *reinterpret_cast<uint32_t*>(&h0);
        u.y = *reinterpret_cast<uint32_t*>(&h1);
        outp[i * 32] = u;
    }
}

// ---------------- chunked SSM scan (fp32 math, fp16 inputs) ----------------
__global__ void scan_passA(const float* __restrict__ A_log) {
    int b = blockIdx.x / NCHUNKS;
    int c = blockIdx.x % NCHUNKS;
    int n = threadIdx.x;
    float Ab = expf(-expf(A_log[n]));
    const __half* base = g_bcx + (size_t)(b * SEQ + c * CHUNK) * 192;
    float h = 0.0f;
    #pragma unroll 8
    for (int t = 0; t < CHUNK; t++) {
        float Bv = __half2float(base[(size_t)t * 192 + n]);
        float xv = __half2float(base[(size_t)t * 192 + 128 + n]);
        h = fmaf(Ab, h, Bv * xv);
    }
    g_chunkend[(b * NCHUNKS + c) * NSTATE + n] = h;
}

__global__ void scan_passB(const float* __restrict__ A_log) {
    int idx = threadIdx.x;
    int b = idx / NSTATE;
    int n = idx % NSTATE;
    float AL = expf(-(float)CHUNK * expf(A_log[n]));
    float h = 0.0f;
    for (int c = 0; c < NCHUNKS; c++) {
        g_hinit[(b * NCHUNKS + c) * NSTATE + n] = h;
        h = fmaf(AL, h, g_chunkend[(b * NCHUNKS + c) * NSTATE + n]);
    }
}

// out: fp16 ch into g_cat cols 0..63
__global__ void scan_passC(const float* __restrict__ A_log) {
    int b = blockIdx.x / NCHUNKS;
    int c = blockIdx.x % NCHUNKS;
    int n = threadIdx.x;
    float Ab = expf(-expf(A_log[n]));
    const __half* base = g_bcx + (size_t)(b * SEQ + c * CHUNK) * 192;
    __half* out = g_cat + (size_t)(b * SEQ + c * CHUNK) * KCAT;
    float h = g_hinit[(b * NCHUNKS + c) * NSTATE + n];
    #pragma unroll 8
    for (int t = 0; t < CHUNK; t++) {
        float Bv = __half2float(base[(size_t)t * 192 + n]);
        float Cv = __half2float(base[(size_t)t * 192 + 64 + n]);
        float xv = __half2float(base[(size_t)t * 192 + 128 + n]);
        h = fmaf(Ab, h, Bv * xv);
        out[(size_t)t * KCAT + n] = __float2half(Cv * h);
    }
}

// ---------------- launch ----------------
extern "C" void kernel_launch(void* const* d_in, const int* in_sizes, int n_in,
                              void* d_out, int out_size) {
    const float* x        = (const float*)d_in[0];
    const float* ln_gamma = (const float*)d_in[1];
    const float* ln_beta  = (const float*)d_in[2];
    const float* W_in     = (const float*)d_in[3];
    const float* b_in     = (const float*)d_in[4];
    const float* W_xs     = (const float*)d_in[5];
    const float* W_B      = (const float*)d_in[6];
    const float* b_B      = (const float*)d_in[7];
    const float* W_C      = (const float*)d_in[8];
    const float* b_C      = (const float*)d_in[9];
    const float* A_log    = (const float*)d_in[10];
    const float* D_skip   = (const float*)d_in[11];
    const float* W_so     = (const float*)d_in[12];
    const float* W_out    = (const float*)d_in[13];
    const float* b_out    = (const float*)d_in[14];
    float* out = (float*)d_out;

    __half* xn;     cudaGetSymbolAddress((void**)&xn,     g_xn);
    __half* cat;    cudaGetSymbolAddress((void**)&cat,    g_cat);
    __half* bcx;    cudaGetSymbolAddress((void**)&bcx,    g_bcx);
    __half* WTin;   cudaGetSymbolAddress((void**)&WTin,   g_WTin);
    __half* WTcat;  cudaGetSymbolAddress((void**)&WTcat,  g_WTcat);
    __half* WTfused;cudaGetSymbolAddress((void**)&WTfused,g_WTfused);
    float* bcat;    cudaGetSymbolAddress((void**)&bcat,   g_bcat);

    const int SMEM64  = 3 * (128 + 64) * 128;    // 73728
    const int SMEM128 = 3 * (128 + 128) * 128;   // 98304
    cudaFuncSetAttribute(mma_gemm<128, 64, 0, 1>, cudaFuncAttributeMaxDynamicSharedMemorySize, SMEM128);
    cudaFuncSetAttribute(mma_gemm<64, 32, 0, 1>,  cudaFuncAttributeMaxDynamicSharedMemorySize, SMEM64);
    cudaFuncSetAttribute(mma_gemm<128, 64, 2, 0>, cudaFuncAttributeMaxDynamicSharedMemorySize, SMEM128);

    // 1) weight prep
    prep_transpose<<<dim3(16, 16), dim3(32, 8)>>>(W_in, W_out, D_skip);
    prep_weights<<<(192 * DMODEL + 255) / 256, 256>>>(W_B, W_C, W_xs, b_B, b_C);
    prep_fused<<<NSTATE, 512>>>(W_so, W_out);

    // 2) LayerNorm -> fp16 (warp per token, coalesced)
    ln_kernel<<<TOKENS / 8, 256>>>(x, ln_gamma, ln_beta);

    // 3) xp = xn @ W_in + b_in -> g_cat cols 64..575 (fp16)
    mma_gemm<128, 64, 0, 1><<<dim3(4, 256), 256, SMEM128>>>(
        xn, DMODEL, WTin, cat + NSTATE, KCAT, b_in, nullptr, DMODEL, DMODEL);

    // 4) [B|C|xs] = xp @ Wcat + bcat (fp16 -> scan), warp tile 32x32
    mma_gemm<64, 32, 0, 1><<<dim3(3, 256), 256, SMEM64>>>(
        cat + NSTATE, KCAT, WTcat, bcx, 192, bcat, nullptr, DMODEL, 192);

    // 5) chunked scan -> ch = fp16(C*h) into g_cat cols 0..63
    scan_passA<<<BATCH * NCHUNKS, NSTATE>>>(A_log);
    scan_passB<<<1, BATCH * NSTATE>>>(A_log);
    scan_passC<<<BATCH * NCHUNKS, NSTATE>>>(A_log);

    // 6) out = [ch | xp] @ WTfused + b_out + x   (K=576, fp32 out)
    mma_gemm<128, 64, 2, 0><<<dim3(4, 256), 256, SMEM128>>>(
        cat, KCAT, WTfused, out, DMODEL, b_out, x, KCAT, DMODEL);
}